// round 1
// baseline (speedup 1.0000x reference)
#include <cuda_runtime.h>
#include <cuda_bf16.h>
#include <math_constants.h>

#define B_   4
#define S_   2048
#define D_   256
#define H_   8
#define HD_  32
#define KEEP 204          // int(2048 * 0.1)
#define ROWS (B_ * S_)    // 8192
#define KV_ROWS (B_ * KEEP) // 816

// ------------------------- scratch (static device globals) -------------------
__device__ float g_importance[ROWS];
__device__ int   g_rowmap[KV_ROWS];            // flat row index into x for kept keys
__device__ float g_Q[ROWS * D_];               // [B,S,256]
__device__ float g_KV[KV_ROWS * 2 * D_];       // [B*KEEP, 512]  cols 0..255 = K, 256..511 = V
__device__ float g_attn[ROWS * D_];            // attention output before out-proj

// ------------------------- gate: importance = sigmoid(MLP(x)) ----------------
__global__ void gate_kernel(const float* __restrict__ x,
                            const float* __restrict__ w1, const float* __restrict__ b1,
                            const float* __restrict__ w2, const float* __restrict__ b2) {
    int warp = (blockIdx.x * blockDim.x + threadIdx.x) >> 5;
    int lane = threadIdx.x & 31;
    if (warp >= ROWS) return;
    const float* xr  = x  + (size_t)warp * D_;
    const float* w1a = w1 + (size_t)lane * D_;
    const float* w1b = w1 + (size_t)(lane + 32) * D_;
    float a0 = 0.f, a1 = 0.f;
    #pragma unroll 8
    for (int d = 0; d < D_; d++) {
        float xv = __ldg(xr + d);
        a0 = fmaf(xv, __ldg(w1a + d), a0);
        a1 = fmaf(xv, __ldg(w1b + d), a1);
    }
    float h0 = fmaxf(a0 + b1[lane], 0.f);
    float h1 = fmaxf(a1 + b1[lane + 32], 0.f);
    float p = h0 * w2[lane] + h1 * w2[lane + 32];
    #pragma unroll
    for (int o = 16; o; o >>= 1) p += __shfl_xor_sync(0xffffffffu, p, o);
    if (lane == 0) g_importance[warp] = 1.f / (1.f + expf(-(p + b2[0])));
}

// ------------------------- top-k per batch (bitonic sort) --------------------
__global__ void topk_kernel() {
    __shared__ unsigned long long keys[S_];
    int b = blockIdx.x;
    int t = threadIdx.x;  // 1024 threads
    for (int i = t; i < S_; i += 1024) {
        unsigned int bits = __float_as_uint(g_importance[b * S_ + i]); // positive -> monotonic
        keys[i] = ((unsigned long long)bits << 32) | (unsigned int)(S_ - 1 - i);
    }
    __syncthreads();
    // descending bitonic sort; ties broken toward lower index (larger low word)
    for (int k = 2; k <= S_; k <<= 1) {
        for (int j = k >> 1; j > 0; j >>= 1) {
            for (int i = t; i < S_; i += 1024) {
                int l = i ^ j;
                if (l > i) {
                    unsigned long long a = keys[i], c = keys[l];
                    bool sw = ((i & k) == 0) ? (a < c) : (a > c);
                    if (sw) { keys[i] = c; keys[l] = a; }
                }
            }
            __syncthreads();
        }
    }
    if (t < KEEP) {
        int idx = (S_ - 1) - (int)(unsigned int)(keys[t] & 0xFFFFFFFFull);
        g_rowmap[b * KEEP + t] = b * S_ + idx;
    }
}

// ------------------------- fp32 NT-GEMM with optional row gather -------------
// C[m, n] = sum_k A[rowmap?rowmap[m]:m, k] * W[n, k] + bias[n]
// BM=BN=64, BK=16, 256 threads, 4x4 microtile. N % 64 == 0, K % 16 == 0.
__global__ __launch_bounds__(256) void gemm_nt(
    const float* __restrict__ A, const int* __restrict__ rowmap,
    const float* __restrict__ W, const float* __restrict__ bias,
    float* __restrict__ C, int M, int N, int K) {
    __shared__ float As[64][17];
    __shared__ float Ws[64][17];
    int tid = threadIdx.x;
    int tx = tid & 15, ty = tid >> 4;
    int rowBase = blockIdx.y * 64;
    int colBase = blockIdx.x * 64;

    float acc[4][4] = {};
    int l  = tid * 4;
    int ar = l >> 4;
    int ac = l & 15;
    int grow = rowBase + ar;
    bool rowOk = (grow < M);
    int  gr = rowOk ? (rowmap ? rowmap[grow] : grow) : 0;
    const float* asrc = A + (size_t)gr * K + ac;
    const float* wsrc = W + (size_t)(colBase + ar) * K + ac;

    for (int k0 = 0; k0 < K; k0 += 16) {
        if (rowOk) {
            As[ar][ac + 0] = asrc[k0 + 0];
            As[ar][ac + 1] = asrc[k0 + 1];
            As[ar][ac + 2] = asrc[k0 + 2];
            As[ar][ac + 3] = asrc[k0 + 3];
        } else {
            As[ar][ac + 0] = 0.f; As[ar][ac + 1] = 0.f;
            As[ar][ac + 2] = 0.f; As[ar][ac + 3] = 0.f;
        }
        Ws[ar][ac + 0] = wsrc[k0 + 0];
        Ws[ar][ac + 1] = wsrc[k0 + 1];
        Ws[ar][ac + 2] = wsrc[k0 + 2];
        Ws[ar][ac + 3] = wsrc[k0 + 3];
        __syncthreads();
        #pragma unroll
        for (int kk = 0; kk < 16; kk++) {
            float a[4], w[4];
            #pragma unroll
            for (int i = 0; i < 4; i++) a[i] = As[ty * 4 + i][kk];
            #pragma unroll
            for (int j = 0; j < 4; j++) w[j] = Ws[tx * 4 + j][kk];
            #pragma unroll
            for (int i = 0; i < 4; i++)
                #pragma unroll
                for (int j = 0; j < 4; j++)
                    acc[i][j] = fmaf(a[i], w[j], acc[i][j]);
        }
        __syncthreads();
    }
    #pragma unroll
    for (int i = 0; i < 4; i++) {
        int r = rowBase + ty * 4 + i;
        if (r < M) {
            float* dst = C + (size_t)r * N + colBase + tx * 4;
            #pragma unroll
            for (int j = 0; j < 4; j++)
                dst[j] = acc[i][j] + bias[colBase + tx * 4 + j];
        }
    }
}

// ------------------------- attention over compacted keys ---------------------
// grid: (B*H, S/128), block 128 threads, one query per thread
__global__ __launch_bounds__(128) void attn_kernel() {
    int bh = blockIdx.x;
    int b = bh >> 3, h = bh & 7;
    int q = blockIdx.y * 128 + threadIdx.x;
    const float scale = 0.17677669529663687f;  // 1/sqrt(32)

    __shared__ float Ks[128][32];
    __shared__ float Vs[128][32];

    float qr[HD_];
    const float* qp = g_Q + ((size_t)(b * S_ + q)) * D_ + h * HD_;
    #pragma unroll
    for (int d = 0; d < HD_; d++) qr[d] = qp[d] * scale;

    float o[HD_] = {};
    float m = -CUDART_INF_F, lsum = 0.f;

    for (int j0 = 0; j0 < KEEP; j0 += 128) {
        int cnt = min(128, KEEP - j0);
        __syncthreads();
        for (int idx = threadIdx.x; idx < cnt * HD_; idx += 128) {
            int r = idx >> 5, c = idx & 31;
            const float* src = g_KV + ((size_t)(b * KEEP + j0 + r)) * (2 * D_) + h * HD_;
            Ks[r][c] = src[c];
            Vs[r][c] = src[D_ + c];
        }
        __syncthreads();
        for (int j = 0; j < cnt; j++) {
            float s = 0.f;
            #pragma unroll
            for (int d = 0; d < HD_; d++) s = fmaf(qr[d], Ks[j][d], s);
            float mn   = fmaxf(m, s);
            float corr = expf(m - mn);   // exp(-inf)=0 on first iter
            float p    = expf(s - mn);
            lsum = lsum * corr + p;
            #pragma unroll
            for (int d = 0; d < HD_; d++) o[d] = fmaf(o[d], corr, p * Vs[j][d]);
            m = mn;
        }
    }
    float inv = 1.f / lsum;
    float* op = g_attn + ((size_t)(b * S_ + q)) * D_ + h * HD_;
    #pragma unroll
    for (int d = 0; d < HD_; d++) op[d] = o[d] * inv;
}

// ------------------------- host launch ---------------------------------------
extern "C" void kernel_launch(void* const* d_in, const int* in_sizes, int n_in,
                              void* d_out, int out_size) {
    const float* x       = (const float*)d_in[0];
    const float* w_in    = (const float*)d_in[1];
    const float* b_in    = (const float*)d_in[2];
    const float* w_out   = (const float*)d_in[3];
    const float* b_out   = (const float*)d_in[4];
    const float* gate_w1 = (const float*)d_in[5];
    const float* gate_b1 = (const float*)d_in[6];
    const float* gate_w2 = (const float*)d_in[7];
    const float* gate_b2 = (const float*)d_in[8];
    float* out = (float*)d_out;

    void *pQ, *pKV, *pAttn, *pRowmap;
    cudaGetSymbolAddress(&pQ, g_Q);
    cudaGetSymbolAddress(&pKV, g_KV);
    cudaGetSymbolAddress(&pAttn, g_attn);
    cudaGetSymbolAddress(&pRowmap, g_rowmap);

    // 1. gate importance  (8192 warps)
    gate_kernel<<<ROWS / 8, 256>>>(x, gate_w1, gate_b1, gate_w2, gate_b2);

    // 2. per-batch top-k -> rowmap
    topk_kernel<<<B_, 1024>>>();

    // 3. Q = x @ Wq^T   [8192 x 256]
    gemm_nt<<<dim3(D_ / 64, ROWS / 64), 256>>>(
        x, nullptr, w_in, b_in, (float*)pQ, ROWS, D_, D_);

    // 4. K,V at kept rows: [816 x 512] = x[rowmap] @ (Wk;Wv)^T
    gemm_nt<<<dim3((2 * D_) / 64, (KV_ROWS + 63) / 64), 256>>>(
        x, (const int*)pRowmap, w_in + D_ * D_, b_in + D_,
        (float*)pKV, KV_ROWS, 2 * D_, D_);

    // 5. attention over 204 compacted keys
    attn_kernel<<<dim3(B_ * H_, S_ / 128), 128>>>();

    // 6. out projection: d_out = attn @ w_out^T + b_out
    gemm_nt<<<dim3(D_ / 64, ROWS / 64), 256>>>(
        (const float*)pAttn, nullptr, w_out, b_out, out, ROWS, D_, D_);
}

// round 2
// speedup vs baseline: 3.0663x; 3.0663x over previous
#include <cuda_runtime.h>
#include <cuda_bf16.h>
#include <math_constants.h>

#define B_   4
#define S_   2048
#define D_   256
#define H_   8
#define HD_  32
#define KEEP 204            // int(2048 * 0.1)
#define ROWS (B_ * S_)      // 8192
#define KV_ROWS (B_ * KEEP) // 816

// ------------------------- scratch (static device globals) -------------------
__device__ float g_importance[ROWS];
__device__ float g_h[ROWS * 64];               // gate hidden layer
__device__ int   g_rowmap[KV_ROWS];            // flat row index into x for kept keys
__device__ float g_Q[ROWS * D_];               // [B,S,256]
__device__ float g_KV[KV_ROWS * 2 * D_];       // [B*KEEP, 512] cols 0..255=K, 256..511=V
__device__ float g_attn[ROWS * D_];            // attention output before out-proj

// ------------------------- fp32 NT-GEMM, 128x64x16 tiles, gather option ------
// C[m,n] = sum_k A[rowmap? rowmap[m] : m, k] * W[n,k] + bias[n]
// 256 threads, 8x4 microtile. Requires N%64==0, K%16==0.
__global__ __launch_bounds__(256) void gemm_nt(
    const float* __restrict__ A, const int* __restrict__ rowmap,
    const float* __restrict__ W, const float* __restrict__ bias,
    float* __restrict__ C, int M, int N, int K) {
    __shared__ float As[16][132];   // K-major, padded
    __shared__ float Ws[16][68];

    int tid = threadIdx.x;
    int rowBase = blockIdx.y * 128;
    int colBase = blockIdx.x * 64;

    // loaders
    int ar = tid & 127;             // row within tile
    int ac = (tid >> 7) * 8;        // k-offset 0 or 8
    int wr = tid & 63;
    int wc = (tid >> 6) * 4;        // 0,4,8,12

    int grow = rowBase + ar;
    bool rowOk = grow < M;
    int gr = rowOk ? (rowmap ? rowmap[grow] : grow) : 0;
    const float* asrc = A + (size_t)gr * K + ac;
    const float* wsrc = W + (size_t)(colBase + wr) * K + wc;

    float4 a0, a1, w0;
    if (rowOk) { a0 = *(const float4*)(asrc); a1 = *(const float4*)(asrc + 4); }
    else       { a0 = make_float4(0,0,0,0); a1 = a0; }
    w0 = *(const float4*)(wsrc);

    int tx = tid & 15, ty = tid >> 4;
    float acc[8][4] = {};

    for (int k0 = 0; k0 < K; k0 += 16) {
        As[ac+0][ar] = a0.x; As[ac+1][ar] = a0.y; As[ac+2][ar] = a0.z; As[ac+3][ar] = a0.w;
        As[ac+4][ar] = a1.x; As[ac+5][ar] = a1.y; As[ac+6][ar] = a1.z; As[ac+7][ar] = a1.w;
        Ws[wc+0][wr] = w0.x; Ws[wc+1][wr] = w0.y; Ws[wc+2][wr] = w0.z; Ws[wc+3][wr] = w0.w;
        __syncthreads();
        if (k0 + 16 < K) {
            if (rowOk) {
                a0 = *(const float4*)(asrc + k0 + 16);
                a1 = *(const float4*)(asrc + k0 + 20);
            }
            w0 = *(const float4*)(wsrc + k0 + 16);
        }
        #pragma unroll
        for (int kk = 0; kk < 16; kk++) {
            float a[8], w[4];
            *(float4*)(a)     = *(const float4*)&As[kk][ty * 8];
            *(float4*)(a + 4) = *(const float4*)&As[kk][ty * 8 + 4];
            *(float4*)(w)     = *(const float4*)&Ws[kk][tx * 4];
            #pragma unroll
            for (int i = 0; i < 8; i++)
                #pragma unroll
                for (int j = 0; j < 4; j++)
                    acc[i][j] = fmaf(a[i], w[j], acc[i][j]);
        }
        __syncthreads();
    }
    float bb[4];
    #pragma unroll
    for (int j = 0; j < 4; j++) bb[j] = bias[colBase + tx * 4 + j];
    #pragma unroll
    for (int i = 0; i < 8; i++) {
        int r = rowBase + ty * 8 + i;
        if (r < M) {
            float* dst = C + (size_t)r * N + colBase + tx * 4;
            #pragma unroll
            for (int j = 0; j < 4; j++) dst[j] = acc[i][j] + bb[j];
        }
    }
}

// ------------------------- gate stage 2: relu, dot w2, sigmoid ---------------
__global__ void gate2_kernel(const float* __restrict__ w2, const float* __restrict__ b2) {
    int warp = (blockIdx.x * blockDim.x + threadIdx.x) >> 5;
    int lane = threadIdx.x & 31;
    if (warp >= ROWS) return;
    float h0 = fmaxf(g_h[warp * 64 + lane], 0.f);
    float h1 = fmaxf(g_h[warp * 64 + 32 + lane], 0.f);
    float p = h0 * w2[lane] + h1 * w2[lane + 32];
    #pragma unroll
    for (int o = 16; o; o >>= 1) p += __shfl_xor_sync(0xffffffffu, p, o);
    if (lane == 0) g_importance[warp] = 1.f / (1.f + expf(-(p + b2[0])));
}

// ------------------------- top-k per batch (bitonic sort) --------------------
__global__ void topk_kernel() {
    __shared__ unsigned long long keys[S_];
    int b = blockIdx.x;
    int t = threadIdx.x;  // 1024 threads
    for (int i = t; i < S_; i += 1024) {
        unsigned int bits = __float_as_uint(g_importance[b * S_ + i]); // positive -> monotonic
        keys[i] = ((unsigned long long)bits << 32) | (unsigned int)(S_ - 1 - i);
    }
    __syncthreads();
    // descending bitonic sort; ties broken toward lower index
    for (int k = 2; k <= S_; k <<= 1) {
        for (int j = k >> 1; j > 0; j >>= 1) {
            for (int i = t; i < S_; i += 1024) {
                int l = i ^ j;
                if (l > i) {
                    unsigned long long a = keys[i], c = keys[l];
                    bool sw = ((i & k) == 0) ? (a < c) : (a > c);
                    if (sw) { keys[i] = c; keys[l] = a; }
                }
            }
            __syncthreads();
        }
    }
    if (t < KEEP) {
        int idx = (S_ - 1) - (int)(unsigned int)(keys[t] & 0xFFFFFFFFull);
        g_rowmap[b * KEEP + t] = b * S_ + idx;
    }
}

// ------------------------- attention over compacted keys ---------------------
// grid: (B*H, S/128), block 128 threads, one query per thread
__global__ __launch_bounds__(128) void attn_kernel() {
    int bh = blockIdx.x;
    int b = bh >> 3, h = bh & 7;
    int q = blockIdx.y * 128 + threadIdx.x;
    const float scale = 0.17677669529663687f;  // 1/sqrt(32)

    __shared__ float Ks[128][32];
    __shared__ float Vs[128][32];

    float qr[HD_];
    const float* qp = g_Q + ((size_t)(b * S_ + q)) * D_ + h * HD_;
    #pragma unroll
    for (int d = 0; d < HD_; d++) qr[d] = qp[d] * scale;

    float o[HD_] = {};
    float m = -CUDART_INF_F, lsum = 0.f;

    for (int j0 = 0; j0 < KEEP; j0 += 128) {
        int cnt = min(128, KEEP - j0);
        __syncthreads();
        for (int idx = threadIdx.x; idx < cnt * HD_; idx += 128) {
            int r = idx >> 5, c = idx & 31;
            const float* src = g_KV + ((size_t)(b * KEEP + j0 + r)) * (2 * D_) + h * HD_;
            Ks[r][c] = src[c];
            Vs[r][c] = src[D_ + c];
        }
        __syncthreads();
        for (int j = 0; j < cnt; j++) {
            float s = 0.f;
            #pragma unroll
            for (int d = 0; d < HD_; d++) s = fmaf(qr[d], Ks[j][d], s);
            float mn   = fmaxf(m, s);
            float corr = expf(m - mn);   // exp(-inf)=0 on first iter
            float p    = expf(s - mn);
            lsum = lsum * corr + p;
            #pragma unroll
            for (int d = 0; d < HD_; d++) o[d] = fmaf(o[d], corr, p * Vs[j][d]);
            m = mn;
        }
    }
    float inv = 1.f / lsum;
    float* op = g_attn + ((size_t)(b * S_ + q)) * D_ + h * HD_;
    #pragma unroll
    for (int d = 0; d < HD_; d++) op[d] = o[d] * inv;
}

// ------------------------- host launch ---------------------------------------
extern "C" void kernel_launch(void* const* d_in, const int* in_sizes, int n_in,
                              void* d_out, int out_size) {
    const float* x       = (const float*)d_in[0];
    const float* w_in    = (const float*)d_in[1];
    const float* b_in    = (const float*)d_in[2];
    const float* w_out   = (const float*)d_in[3];
    const float* b_out   = (const float*)d_in[4];
    const float* gate_w1 = (const float*)d_in[5];
    const float* gate_b1 = (const float*)d_in[6];
    const float* gate_w2 = (const float*)d_in[7];
    const float* gate_b2 = (const float*)d_in[8];
    float* out = (float*)d_out;

    void *pQ, *pKV, *pAttn, *pRowmap, *pH;
    cudaGetSymbolAddress(&pQ, g_Q);
    cudaGetSymbolAddress(&pKV, g_KV);
    cudaGetSymbolAddress(&pAttn, g_attn);
    cudaGetSymbolAddress(&pRowmap, g_rowmap);
    cudaGetSymbolAddress(&pH, g_h);

    // 1. gate hidden layer as GEMM: h = x @ gate_w1^T + b1   [8192 x 64]
    gemm_nt<<<dim3(1, ROWS / 128), 256>>>(
        x, nullptr, gate_w1, gate_b1, (float*)pH, ROWS, 64, D_);

    // 2. relu + dot(w2) + sigmoid -> importance
    gate2_kernel<<<ROWS / 8, 256>>>(gate_w2, gate_b2);

    // 3. per-batch top-k -> rowmap
    topk_kernel<<<B_, 1024>>>();

    // 4. Q = x @ Wq^T   [8192 x 256]
    gemm_nt<<<dim3(D_ / 64, ROWS / 128), 256>>>(
        x, nullptr, w_in, b_in, (float*)pQ, ROWS, D_, D_);

    // 5. K,V at kept rows: [816 x 512] = x[rowmap] @ (Wk;Wv)^T
    gemm_nt<<<dim3((2 * D_) / 64, (KV_ROWS + 127) / 128), 256>>>(
        x, (const int*)pRowmap, w_in + D_ * D_, b_in + D_,
        (float*)pKV, KV_ROWS, 2 * D_, D_);

    // 6. attention over 204 compacted keys
    attn_kernel<<<dim3(B_ * H_, S_ / 128), 128>>>();

    // 7. out projection: d_out = attn @ w_out^T + b_out
    gemm_nt<<<dim3(D_ / 64, ROWS / 128), 256>>>(
        (const float*)pAttn, nullptr, w_out, b_out, out, ROWS, D_, D_);
}

// round 4
// speedup vs baseline: 3.6013x; 1.1745x over previous
#include <cuda_runtime.h>
#include <cuda_bf16.h>
#include <math_constants.h>
#include <cstdint>

#define B_   4
#define S_   2048
#define D_   256
#define H_   8
#define HD_  32
#define KEEP 204            // int(2048 * 0.1)
#define ROWS (B_ * S_)      // 8192
#define KV_ROWS (B_ * KEEP) // 816

// ------------------------- scratch (static device globals) -------------------
__device__ float g_importance[ROWS];
__device__ float g_h[ROWS * 64];               // gate hidden layer
__device__ int   g_rowmap[KV_ROWS];            // flat row index into x for kept keys
__device__ float g_Q[ROWS * D_];               // [B,S,256]
__device__ float g_KV[KV_ROWS * 2 * D_];       // [B*KEEP, 512] cols 0..255=K, 256..511=V
__device__ float g_attn[ROWS * D_];            // attention output before out-proj

// ========================= mma.sync helpers (plain sm_103 ISA) ================
__device__ __forceinline__ uint32_t smem_u32(const void* p) {
    uint32_t a;
    asm("{ .reg .u64 t; cvta.to.shared.u64 t, %1; cvt.u32.u64 %0, t; }" : "=r"(a) : "l"(p));
    return a;
}
__device__ __forceinline__ void ldsm_x4(uint32_t& r0, uint32_t& r1, uint32_t& r2,
                                        uint32_t& r3, uint32_t addr) {
    asm volatile("ldmatrix.sync.aligned.m8n8.x4.shared.b16 {%0,%1,%2,%3}, [%4];"
                 : "=r"(r0), "=r"(r1), "=r"(r2), "=r"(r3) : "r"(addr));
}
__device__ __forceinline__ void mma_bf16(float* c, const uint32_t* a, const uint32_t* b) {
    asm volatile("mma.sync.aligned.m16n8k16.row.col.f32.bf16.bf16.f32 "
                 "{%0,%1,%2,%3}, {%4,%5,%6,%7}, {%8,%9}, {%0,%1,%2,%3};"
                 : "+f"(c[0]), "+f"(c[1]), "+f"(c[2]), "+f"(c[3])
                 : "r"(a[0]), "r"(a[1]), "r"(a[2]), "r"(a[3]), "r"(b[0]), "r"(b[1]));
}

// ========================= bf16x3 MMA GEMM ====================================
// C[m,n] = sum_k A[rowmap? rowmap[m] : m, k] * W[n,k] + bias[n],  K = 256 fixed.
// CTA: 128x64 tile, 256 threads (8 warps, 2x4), warp tile 64x16. Full K in smem.
#define TM 128
#define TN 64
#define KD 256
#define KP (KD + 8)                         // +16B pad per row -> conflict-free ldmatrix
#define SM_AHI 0
#define SM_ALO (SM_AHI + TM * KP * 2)       // 67584
#define SM_BHI (SM_ALO + TM * KP * 2)       // 135168
#define SM_BLO (SM_BHI + TN * KP * 2)       // 168960
#define SMEM_MM (SM_BLO + TN * KP * 2)      // 202752 bytes

__global__ __launch_bounds__(256, 1) void gemm_mma(
    const float* __restrict__ A, const int* __restrict__ rowmap,
    const float* __restrict__ W, const float* __restrict__ bias,
    float* __restrict__ C, int M, int N) {
    extern __shared__ char smem[];
    uint32_t sb = smem_u32(smem);
    int tid = threadIdx.x, wid = tid >> 5, lane = tid & 31;
    int rowBase = blockIdx.y * TM, colBase = blockIdx.x * TN;
    int warp_m = (wid >> 2) * 64;           // 0 or 64
    int warp_n = (wid & 3) * 16;            // 0,16,32,48

    // ---- load + hi/lo split A tile (128 x 256) ----
    for (int i = tid; i < TM * (KD / 2); i += 256) {
        int r = i >> 7, c = (i & 127) * 2;
        int grow = rowBase + r;
        float2 v = make_float2(0.f, 0.f);
        if (grow < M) {
            int gr = rowmap ? rowmap[grow] : grow;
            v = *(const float2*)(A + (size_t)gr * KD + c);
        }
        __nv_bfloat16 hx = __float2bfloat16(v.x), hy = __float2bfloat16(v.y);
        __nv_bfloat16 lx = __float2bfloat16(v.x - __bfloat162float(hx));
        __nv_bfloat16 ly = __float2bfloat16(v.y - __bfloat162float(hy));
        uint32_t off = (uint32_t)(r * KP + c) * 2;
        *(__nv_bfloat162*)(smem + SM_AHI + off) = __halves2bfloat162(hx, hy);
        *(__nv_bfloat162*)(smem + SM_ALO + off) = __halves2bfloat162(lx, ly);
    }
    // ---- load + hi/lo split B tile (64 x 256) ----
    for (int i = tid; i < TN * (KD / 2); i += 256) {
        int r = i >> 7, c = (i & 127) * 2;
        float2 v = *(const float2*)(W + (size_t)(colBase + r) * KD + c);
        __nv_bfloat16 hx = __float2bfloat16(v.x), hy = __float2bfloat16(v.y);
        __nv_bfloat16 lx = __float2bfloat16(v.x - __bfloat162float(hx));
        __nv_bfloat16 ly = __float2bfloat16(v.y - __bfloat162float(hy));
        uint32_t off = (uint32_t)(r * KP + c) * 2;
        *(__nv_bfloat162*)(smem + SM_BHI + off) = __halves2bfloat162(hx, hy);
        *(__nv_bfloat162*)(smem + SM_BLO + off) = __halves2bfloat162(lx, ly);
    }
    __syncthreads();

    // ---- fragment base addresses (k0 = 0) ----
    // A: per m-frag mf: row = warp_m + mf*16 + (lane&15), k-col = (lane>>4)*8
    uint32_t a_base[4];
    #pragma unroll
    for (int mf = 0; mf < 4; mf++) {
        int row = warp_m + mf * 16 + (lane & 15);
        a_base[mf] = sb + (uint32_t)(row * KP + (lane >> 4) * 8) * 2;
    }
    // B x4: lane group g = lane>>3, r = lane&7: n-row = warp_n + (g>>1)*8 + r, k-col = (g&1)*8
    int bg = lane >> 3, br = lane & 7;
    uint32_t b_base = sb + (uint32_t)((warp_n + (bg >> 1) * 8 + br) * KP + (bg & 1) * 8) * 2;

    float acc[4][2][4] = {};   // [m-frag][n-frag][c0..c3]

    #pragma unroll 4
    for (int ks = 0; ks < 16; ks++) {
        uint32_t koff = (uint32_t)(ks * 16) * 2;
        uint32_t bh[2][2], bl[2][2], a[4][4];
        ldsm_x4(bh[0][0], bh[0][1], bh[1][0], bh[1][1], b_base + SM_BHI + koff);
        ldsm_x4(bl[0][0], bl[0][1], bl[1][0], bl[1][1], b_base + SM_BLO + koff);
        // pass 1+2: A_hi x (B_hi, B_lo)
        #pragma unroll
        for (int mf = 0; mf < 4; mf++)
            ldsm_x4(a[mf][0], a[mf][1], a[mf][2], a[mf][3], a_base[mf] + SM_AHI + koff);
        #pragma unroll
        for (int mf = 0; mf < 4; mf++) {
            #pragma unroll
            for (int nf = 0; nf < 2; nf++) {
                mma_bf16(acc[mf][nf], a[mf], bh[nf]);
                mma_bf16(acc[mf][nf], a[mf], bl[nf]);
            }
        }
        // pass 3: A_lo x B_hi
        #pragma unroll
        for (int mf = 0; mf < 4; mf++)
            ldsm_x4(a[mf][0], a[mf][1], a[mf][2], a[mf][3], a_base[mf] + SM_ALO + koff);
        #pragma unroll
        for (int mf = 0; mf < 4; mf++) {
            #pragma unroll
            for (int nf = 0; nf < 2; nf++)
                mma_bf16(acc[mf][nf], a[mf], bh[nf]);
        }
    }

    // ---- epilogue: direct global stores (c0,c1)->(m, n..n+1), (c2,c3)->(m+8) ----
    #pragma unroll
    for (int mf = 0; mf < 4; mf++) {
        #pragma unroll
        for (int nf = 0; nf < 2; nf++) {
            int n = colBase + warp_n + nf * 8 + (lane & 3) * 2;
            float b0 = __ldg(bias + n), b1 = __ldg(bias + n + 1);
            int m0 = rowBase + warp_m + mf * 16 + (lane >> 2);
            if (m0 < M)
                *(float2*)(C + (size_t)m0 * N + n) =
                    make_float2(acc[mf][nf][0] + b0, acc[mf][nf][1] + b1);
            int m1 = m0 + 8;
            if (m1 < M)
                *(float2*)(C + (size_t)m1 * N + n) =
                    make_float2(acc[mf][nf][2] + b0, acc[mf][nf][3] + b1);
        }
    }
}

// ------------------------- fp32 NT-GEMM (gate only; exact path) --------------
__global__ __launch_bounds__(256) void gemm_nt(
    const float* __restrict__ A, const int* __restrict__ rowmap,
    const float* __restrict__ W, const float* __restrict__ bias,
    float* __restrict__ C, int M, int N, int K) {
    __shared__ float As[16][132];
    __shared__ float Ws[16][68];
    int tid = threadIdx.x;
    int rowBase = blockIdx.y * 128;
    int colBase = blockIdx.x * 64;
    int ar = tid & 127, ac = (tid >> 7) * 8;
    int wr = tid & 63,  wc = (tid >> 6) * 4;
    int grow = rowBase + ar;
    bool rowOk = grow < M;
    int gr = rowOk ? (rowmap ? rowmap[grow] : grow) : 0;
    const float* asrc = A + (size_t)gr * K + ac;
    const float* wsrc = W + (size_t)(colBase + wr) * K + wc;
    float4 a0, a1, w0;
    if (rowOk) { a0 = *(const float4*)(asrc); a1 = *(const float4*)(asrc + 4); }
    else       { a0 = make_float4(0,0,0,0); a1 = a0; }
    w0 = *(const float4*)(wsrc);
    int tx = tid & 15, ty = tid >> 4;
    float acc[8][4] = {};
    for (int k0 = 0; k0 < K; k0 += 16) {
        As[ac+0][ar]=a0.x; As[ac+1][ar]=a0.y; As[ac+2][ar]=a0.z; As[ac+3][ar]=a0.w;
        As[ac+4][ar]=a1.x; As[ac+5][ar]=a1.y; As[ac+6][ar]=a1.z; As[ac+7][ar]=a1.w;
        Ws[wc+0][wr]=w0.x; Ws[wc+1][wr]=w0.y; Ws[wc+2][wr]=w0.z; Ws[wc+3][wr]=w0.w;
        __syncthreads();
        if (k0 + 16 < K) {
            if (rowOk) { a0 = *(const float4*)(asrc+k0+16); a1 = *(const float4*)(asrc+k0+20); }
            w0 = *(const float4*)(wsrc + k0 + 16);
        }
        #pragma unroll
        for (int kk = 0; kk < 16; kk++) {
            float a[8], w[4];
            *(float4*)(a)   = *(const float4*)&As[kk][ty*8];
            *(float4*)(a+4) = *(const float4*)&As[kk][ty*8+4];
            *(float4*)(w)   = *(const float4*)&Ws[kk][tx*4];
            #pragma unroll
            for (int i = 0; i < 8; i++)
                #pragma unroll
                for (int j = 0; j < 4; j++)
                    acc[i][j] = fmaf(a[i], w[j], acc[i][j]);
        }
        __syncthreads();
    }
    float bb[4];
    #pragma unroll
    for (int j = 0; j < 4; j++) bb[j] = bias[colBase + tx*4 + j];
    #pragma unroll
    for (int i = 0; i < 8; i++) {
        int r = rowBase + ty*8 + i;
        if (r < M) {
            float* dst = C + (size_t)r * N + colBase + tx*4;
            #pragma unroll
            for (int j = 0; j < 4; j++) dst[j] = acc[i][j] + bb[j];
        }
    }
}

// ------------------------- gate stage 2: relu, dot w2, sigmoid ---------------
__global__ void gate2_kernel(const float* __restrict__ w2, const float* __restrict__ b2) {
    int warp = (blockIdx.x * blockDim.x + threadIdx.x) >> 5;
    int lane = threadIdx.x & 31;
    if (warp >= ROWS) return;
    float h0 = fmaxf(g_h[warp * 64 + lane], 0.f);
    float h1 = fmaxf(g_h[warp * 64 + 32 + lane], 0.f);
    float p = h0 * w2[lane] + h1 * w2[lane + 32];
    #pragma unroll
    for (int o = 16; o; o >>= 1) p += __shfl_xor_sync(0xffffffffu, p, o);
    if (lane == 0) g_importance[warp] = 1.f / (1.f + expf(-(p + b2[0])));
}

// ------------------------- top-k per batch (bitonic sort) --------------------
__global__ void topk_kernel() {
    __shared__ unsigned long long keys[S_];
    int b = blockIdx.x;
    int t = threadIdx.x;
    for (int i = t; i < S_; i += 1024) {
        unsigned int bits = __float_as_uint(g_importance[b * S_ + i]);
        keys[i] = ((unsigned long long)bits << 32) | (unsigned int)(S_ - 1 - i);
    }
    __syncthreads();
    for (int k = 2; k <= S_; k <<= 1) {
        for (int j = k >> 1; j > 0; j >>= 1) {
            for (int i = t; i < S_; i += 1024) {
                int l = i ^ j;
                if (l > i) {
                    unsigned long long a = keys[i], c = keys[l];
                    bool sw = ((i & k) == 0) ? (a < c) : (a > c);
                    if (sw) { keys[i] = c; keys[l] = a; }
                }
            }
            __syncthreads();
        }
    }
    if (t < KEEP) {
        int idx = (S_ - 1) - (int)(unsigned int)(keys[t] & 0xFFFFFFFFull);
        g_rowmap[b * KEEP + t] = b * S_ + idx;
    }
}

// ------------------------- attention over compacted keys ---------------------
__global__ __launch_bounds__(128) void attn_kernel() {
    int bh = blockIdx.x;
    int b = bh >> 3, h = bh & 7;
    int q = blockIdx.y * 128 + threadIdx.x;
    const float scale = 0.17677669529663687f;  // 1/sqrt(32)

    __shared__ float Ks[128][32];
    __shared__ float Vs[128][32];

    float qr[HD_];
    const float* qp = g_Q + ((size_t)(b * S_ + q)) * D_ + h * HD_;
    #pragma unroll
    for (int d = 0; d < HD_; d++) qr[d] = qp[d] * scale;

    float o[HD_] = {};
    float m = -CUDART_INF_F, lsum = 0.f;

    for (int j0 = 0; j0 < KEEP; j0 += 128) {
        int cnt = min(128, KEEP - j0);
        __syncthreads();
        for (int idx = threadIdx.x; idx < cnt * HD_; idx += 128) {
            int r = idx >> 5, c = idx & 31;
            const float* src = g_KV + ((size_t)(b * KEEP + j0 + r)) * (2 * D_) + h * HD_;
            Ks[r][c] = src[c];
            Vs[r][c] = src[D_ + c];
        }
        __syncthreads();
        for (int j = 0; j < cnt; j++) {
            float s = 0.f;
            #pragma unroll
            for (int d = 0; d < HD_; d++) s = fmaf(qr[d], Ks[j][d], s);
            float mn   = fmaxf(m, s);
            float corr = __expf(m - mn);
            float p    = __expf(s - mn);
            lsum = lsum * corr + p;
            #pragma unroll
            for (int d = 0; d < HD_; d++) o[d] = fmaf(o[d], corr, p * Vs[j][d]);
            m = mn;
        }
    }
    float inv = 1.f / lsum;
    float* op = g_attn + ((size_t)(b * S_ + q)) * D_ + h * HD_;
    #pragma unroll
    for (int d = 0; d < HD_; d++) op[d] = o[d] * inv;
}

// ------------------------- host launch ---------------------------------------
extern "C" void kernel_launch(void* const* d_in, const int* in_sizes, int n_in,
                              void* d_out, int out_size) {
    const float* x       = (const float*)d_in[0];
    const float* w_in    = (const float*)d_in[1];
    const float* b_in    = (const float*)d_in[2];
    const float* w_out   = (const float*)d_in[3];
    const float* b_out   = (const float*)d_in[4];
    const float* gate_w1 = (const float*)d_in[5];
    const float* gate_b1 = (const float*)d_in[6];
    const float* gate_w2 = (const float*)d_in[7];
    const float* gate_b2 = (const float*)d_in[8];
    float* out = (float*)d_out;

    void *pQ, *pKV, *pAttn, *pRowmap, *pH;
    cudaGetSymbolAddress(&pQ, g_Q);
    cudaGetSymbolAddress(&pKV, g_KV);
    cudaGetSymbolAddress(&pAttn, g_attn);
    cudaGetSymbolAddress(&pRowmap, g_rowmap);
    cudaGetSymbolAddress(&pH, g_h);

    cudaFuncSetAttribute(gemm_mma, cudaFuncAttributeMaxDynamicSharedMemorySize, SMEM_MM);

    // 1. gate hidden layer (exact fp32 — feeds discrete top-k)
    gemm_nt<<<dim3(1, ROWS / 128), 256>>>(
        x, nullptr, gate_w1, gate_b1, (float*)pH, ROWS, 64, D_);

    // 2. relu + dot(w2) + sigmoid -> importance
    gate2_kernel<<<ROWS / 8, 256>>>(gate_w2, gate_b2);

    // 3. per-batch top-k -> rowmap
    topk_kernel<<<B_, 1024>>>();

    // 4. Q = x @ Wq^T  (mma bf16x3)
    gemm_mma<<<dim3(D_ / TN, ROWS / TM), 256, SMEM_MM>>>(
        x, nullptr, w_in, b_in, (float*)pQ, ROWS, D_);

    // 5. K,V at kept rows (mma bf16x3, gathered)
    gemm_mma<<<dim3((2 * D_) / TN, (KV_ROWS + TM - 1) / TM), 256, SMEM_MM>>>(
        x, (const int*)pRowmap, w_in + D_ * D_, b_in + D_, (float*)pKV, KV_ROWS, 2 * D_);

    // 6. attention over 204 compacted keys
    attn_kernel<<<dim3(B_ * H_, S_ / 128), 128>>>();

    // 7. out projection (mma bf16x3)
    gemm_mma<<<dim3(D_ / TN, ROWS / TM), 256, SMEM_MM>>>(
        (const float*)pAttn, nullptr, w_out, b_out, out, ROWS, D_);
}

// round 5
// speedup vs baseline: 3.7623x; 1.0447x over previous
#include <cuda_runtime.h>
#include <cuda_bf16.h>
#include <math_constants.h>
#include <cstdint>

#define B_   4
#define S_   2048
#define D_   256
#define H_   8
#define HD_  32
#define KEEP 204            // int(2048 * 0.1)
#define ROWS (B_ * S_)      // 8192
#define KV_ROWS (B_ * KEEP) // 816
#define KD   256

// ------------------------- scratch (static device globals) -------------------
__device__ float g_importance[ROWS];
__device__ float g_h[ROWS * 64];
__device__ int   g_rowmap[KV_ROWS];
__device__ float g_Q[ROWS * D_];
__device__ float g_KV[KV_ROWS * 2 * D_];
__device__ float g_attn[ROWS * D_];
// bf16 hi/lo pre-split operands
__device__ __nv_bfloat16 g_xhi[ROWS * D_],   g_xlo[ROWS * D_];
__device__ __nv_bfloat16 g_athi[ROWS * D_],  g_atlo[ROWS * D_];
__device__ __nv_bfloat16 g_winhi[3 * D_ * D_], g_winlo[3 * D_ * D_];
__device__ __nv_bfloat16 g_wouthi[D_ * D_],  g_woutlo[D_ * D_];

// ========================= helpers ============================================
__device__ __forceinline__ uint32_t smem_u32(const void* p) {
    uint32_t a;
    asm("{ .reg .u64 t; cvta.to.shared.u64 t, %1; cvt.u32.u64 %0, t; }" : "=r"(a) : "l"(p));
    return a;
}
__device__ __forceinline__ void ldsm_x4(uint32_t& r0, uint32_t& r1, uint32_t& r2,
                                        uint32_t& r3, uint32_t addr) {
    asm volatile("ldmatrix.sync.aligned.m8n8.x4.shared.b16 {%0,%1,%2,%3}, [%4];"
                 : "=r"(r0), "=r"(r1), "=r"(r2), "=r"(r3) : "r"(addr));
}
__device__ __forceinline__ void mma_bf16(float* c, const uint32_t* a, const uint32_t* b) {
    asm volatile("mma.sync.aligned.m16n8k16.row.col.f32.bf16.bf16.f32 "
                 "{%0,%1,%2,%3}, {%4,%5,%6,%7}, {%8,%9}, {%0,%1,%2,%3};"
                 : "+f"(c[0]), "+f"(c[1]), "+f"(c[2]), "+f"(c[3])
                 : "r"(a[0]), "r"(a[1]), "r"(a[2]), "r"(a[3]), "r"(b[0]), "r"(b[1]));
}
#define CP16(dst, src) \
    asm volatile("cp.async.cg.shared.global [%0], [%1], 16;" :: "r"(dst), "l"(src))
#define CP_COMMIT() asm volatile("cp.async.commit_group;" ::: "memory")
#define CP_WAIT(n)  asm volatile("cp.async.wait_group %0;" :: "n"(n) : "memory")

// ------------------------- fp32 -> bf16 hi/lo split ---------------------------
__global__ void convert_split(const float4* __restrict__ src,
                              __nv_bfloat162* __restrict__ hi,
                              __nv_bfloat162* __restrict__ lo, int n4) {
    int i = blockIdx.x * blockDim.x + threadIdx.x;
    if (i >= n4) return;
    float4 v = src[i];
    __nv_bfloat16 hx = __float2bfloat16(v.x), hy = __float2bfloat16(v.y);
    __nv_bfloat16 hz = __float2bfloat16(v.z), hw = __float2bfloat16(v.w);
    hi[2*i]   = __halves2bfloat162(hx, hy);
    hi[2*i+1] = __halves2bfloat162(hz, hw);
    lo[2*i]   = __halves2bfloat162(__float2bfloat16(v.x - __bfloat162float(hx)),
                                   __float2bfloat16(v.y - __bfloat162float(hy)));
    lo[2*i+1] = __halves2bfloat162(__float2bfloat16(v.z - __bfloat162float(hz)),
                                   __float2bfloat16(v.w - __bfloat162float(hw)));
}

// ========================= pipelined bf16x3 GEMM ==============================
// C[m,n] = sum_k A[rowmap? rowmap[m]:m, k] * W[n,k] + bias[n],  K=256.
// 128x128 tile, BK=32, 2-stage cp.async pipeline, 8 warps (2x4), warp 64x32.
#define GKP 80                                   // padded row stride in BYTES (40 bf16)
#define ST_A_HI 0
#define ST_A_LO 10240
#define ST_B_HI 20480
#define ST_B_LO 30720
#define ST_SIZE 40960
#define SMEM_GM (2 * ST_SIZE)                    // 81920 B

__global__ __launch_bounds__(256) void gemm_bf16(
    const __nv_bfloat16* __restrict__ Ahi, const __nv_bfloat16* __restrict__ Alo,
    const int* __restrict__ rowmap,
    const __nv_bfloat16* __restrict__ Bhi, const __nv_bfloat16* __restrict__ Blo,
    const float* __restrict__ bias, float* __restrict__ C, int M, int N) {
    extern __shared__ char smem[];
    uint32_t sb = smem_u32(smem);
    int tid = threadIdx.x, wid = tid >> 5, lane = tid & 31;
    int rowBase = blockIdx.y * 128, colBase = blockIdx.x * 128;
    int warp_m = (wid >> 2) * 64;                // 0 | 64
    int warp_n = (wid & 3) * 32;                 // 0,32,64,96

    // ---- loader setup: 2 16B chunks per thread per array ----
    int id0 = tid * 2, id1 = id0 + 1;
    int r0 = id0 >> 2, c0 = id0 & 3;             // row 0..127, chunk 0..3 (8 bf16)
    int r1 = id1 >> 2, c1 = id1 & 3;
    int ga0 = (rowBase + r0 < M) ? (rowmap ? rowmap[rowBase + r0] : rowBase + r0) : 0;
    int ga1 = (rowBase + r1 < M) ? (rowmap ? rowmap[rowBase + r1] : rowBase + r1) : 0;
    const __nv_bfloat16* sAh0 = Ahi + (size_t)ga0 * KD + c0 * 8;
    const __nv_bfloat16* sAh1 = Ahi + (size_t)ga1 * KD + c1 * 8;
    const __nv_bfloat16* sAl0 = Alo + (size_t)ga0 * KD + c0 * 8;
    const __nv_bfloat16* sAl1 = Alo + (size_t)ga1 * KD + c1 * 8;
    const __nv_bfloat16* sBh0 = Bhi + (size_t)(colBase + r0) * KD + c0 * 8;
    const __nv_bfloat16* sBh1 = Bhi + (size_t)(colBase + r1) * KD + c1 * 8;
    const __nv_bfloat16* sBl0 = Blo + (size_t)(colBase + r0) * KD + c0 * 8;
    const __nv_bfloat16* sBl1 = Blo + (size_t)(colBase + r1) * KD + c1 * 8;
    uint32_t d0 = sb + (uint32_t)(r0 * GKP + c0 * 16);
    uint32_t d1 = sb + (uint32_t)(r1 * GKP + c1 * 16);

    auto issue = [&](int kt, int st) {
        uint32_t so = (uint32_t)st * ST_SIZE;
        int ko = kt * 32;
        CP16(d0 + so + ST_A_HI, sAh0 + ko);  CP16(d1 + so + ST_A_HI, sAh1 + ko);
        CP16(d0 + so + ST_A_LO, sAl0 + ko);  CP16(d1 + so + ST_A_LO, sAl1 + ko);
        CP16(d0 + so + ST_B_HI, sBh0 + ko);  CP16(d1 + so + ST_B_HI, sBh1 + ko);
        CP16(d0 + so + ST_B_LO, sBl0 + ko);  CP16(d1 + so + ST_B_LO, sBl1 + ko);
        CP_COMMIT();
    };

    // ---- fragment relative byte offsets within a stage ----
    uint32_t arel[4];
    #pragma unroll
    for (int mf = 0; mf < 4; mf++)
        arel[mf] = (uint32_t)((warp_m + mf * 16 + (lane & 15)) * GKP + (lane >> 4) * 16);
    int bg = lane >> 3, br = lane & 7;
    uint32_t brel0 = (uint32_t)((warp_n + (bg >> 1) * 8 + br) * GKP + (bg & 1) * 16);
    uint32_t brel1 = brel0 + 16 * GKP;

    float acc[4][4][4] = {};                      // [mf][nf][4]

    issue(0, 0);
    #pragma unroll 1
    for (int kt = 0; kt < 8; kt++) {
        int st = kt & 1;
        if (kt + 1 < 8) { issue(kt + 1, (kt + 1) & 1); CP_WAIT(1); }
        else            { CP_WAIT(0); }
        __syncthreads();
        uint32_t base = sb + (uint32_t)st * ST_SIZE;
        #pragma unroll
        for (int kc = 0; kc < 2; kc++) {
            uint32_t koff = (uint32_t)kc * 32;
            uint32_t bh[4][2], bl[4][2];
            ldsm_x4(bh[0][0], bh[0][1], bh[1][0], bh[1][1], base + ST_B_HI + brel0 + koff);
            ldsm_x4(bh[2][0], bh[2][1], bh[3][0], bh[3][1], base + ST_B_HI + brel1 + koff);
            ldsm_x4(bl[0][0], bl[0][1], bl[1][0], bl[1][1], base + ST_B_LO + brel0 + koff);
            ldsm_x4(bl[2][0], bl[2][1], bl[3][0], bl[3][1], base + ST_B_LO + brel1 + koff);
            #pragma unroll
            for (int mf = 0; mf < 4; mf++) {
                uint32_t ah[4], al[4];
                ldsm_x4(ah[0], ah[1], ah[2], ah[3], base + ST_A_HI + arel[mf] + koff);
                ldsm_x4(al[0], al[1], al[2], al[3], base + ST_A_LO + arel[mf] + koff);
                #pragma unroll
                for (int nf = 0; nf < 4; nf++) {
                    mma_bf16(acc[mf][nf], ah, bh[nf]);
                    mma_bf16(acc[mf][nf], ah, bl[nf]);
                    mma_bf16(acc[mf][nf], al, bh[nf]);
                }
            }
        }
        __syncthreads();
    }

    // ---- epilogue: direct stores + bias ----
    #pragma unroll
    for (int mf = 0; mf < 4; mf++) {
        #pragma unroll
        for (int nf = 0; nf < 4; nf++) {
            int n = colBase + warp_n + nf * 8 + (lane & 3) * 2;
            float b0 = __ldg(bias + n), b1 = __ldg(bias + n + 1);
            int m0 = rowBase + warp_m + mf * 16 + (lane >> 2);
            if (m0 < M)
                *(float2*)(C + (size_t)m0 * N + n) =
                    make_float2(acc[mf][nf][0] + b0, acc[mf][nf][1] + b1);
            int m1 = m0 + 8;
            if (m1 < M)
                *(float2*)(C + (size_t)m1 * N + n) =
                    make_float2(acc[mf][nf][2] + b0, acc[mf][nf][3] + b1);
        }
    }
}

// ------------------------- gate GEMM (exact fp32, 64-row tiles) --------------
__global__ __launch_bounds__(256) void gate_gemm(
    const float* __restrict__ A, const float* __restrict__ W,
    const float* __restrict__ bias, float* __restrict__ C) {
    // M tile 64, N = 64, K = 256
    __shared__ float As[16][68];
    __shared__ float Ws[16][68];
    int tid = threadIdx.x;
    int rowBase = blockIdx.x * 64;
    int ar = tid & 63, ac = (tid >> 6) * 4;
    const float* asrc = A + (size_t)(rowBase + ar) * KD + ac;
    const float* wsrc = W + (size_t)ar * KD + ac;
    float4 a0 = *(const float4*)asrc;
    float4 w0 = *(const float4*)wsrc;
    int tx = tid & 15, ty = tid >> 4;
    float acc[4][4] = {};
    for (int k0 = 0; k0 < KD; k0 += 16) {
        As[ac+0][ar]=a0.x; As[ac+1][ar]=a0.y; As[ac+2][ar]=a0.z; As[ac+3][ar]=a0.w;
        Ws[ac+0][ar]=w0.x; Ws[ac+1][ar]=w0.y; Ws[ac+2][ar]=w0.z; Ws[ac+3][ar]=w0.w;
        __syncthreads();
        if (k0 + 16 < KD) {
            a0 = *(const float4*)(asrc + k0 + 16);
            w0 = *(const float4*)(wsrc + k0 + 16);
        }
        #pragma unroll
        for (int kk = 0; kk < 16; kk++) {
            float a[4], w[4];
            *(float4*)a = *(const float4*)&As[kk][ty * 4];
            *(float4*)w = *(const float4*)&Ws[kk][tx * 4];
            #pragma unroll
            for (int i = 0; i < 4; i++)
                #pragma unroll
                for (int j = 0; j < 4; j++)
                    acc[i][j] = fmaf(a[i], w[j], acc[i][j]);
        }
        __syncthreads();
    }
    #pragma unroll
    for (int i = 0; i < 4; i++) {
        float* dst = C + (size_t)(rowBase + ty * 4 + i) * 64 + tx * 4;
        #pragma unroll
        for (int j = 0; j < 4; j++) dst[j] = acc[i][j] + bias[tx * 4 + j];
    }
}

// ------------------------- gate stage 2 ---------------------------------------
__global__ void gate2_kernel(const float* __restrict__ w2, const float* __restrict__ b2) {
    int warp = (blockIdx.x * blockDim.x + threadIdx.x) >> 5;
    int lane = threadIdx.x & 31;
    if (warp >= ROWS) return;
    float h0 = fmaxf(g_h[warp * 64 + lane], 0.f);
    float h1 = fmaxf(g_h[warp * 64 + 32 + lane], 0.f);
    float p = h0 * w2[lane] + h1 * w2[lane + 32];
    #pragma unroll
    for (int o = 16; o; o >>= 1) p += __shfl_xor_sync(0xffffffffu, p, o);
    if (lane == 0) g_importance[warp] = 1.f / (1.f + expf(-(p + b2[0])));
}

// ------------------------- top-k per batch (bitonic sort) --------------------
__global__ void topk_kernel() {
    __shared__ unsigned long long keys[S_];
    int b = blockIdx.x;
    int t = threadIdx.x;
    for (int i = t; i < S_; i += 1024) {
        unsigned int bits = __float_as_uint(g_importance[b * S_ + i]);
        keys[i] = ((unsigned long long)bits << 32) | (unsigned int)(S_ - 1 - i);
    }
    __syncthreads();
    for (int k = 2; k <= S_; k <<= 1) {
        for (int j = k >> 1; j > 0; j >>= 1) {
            for (int i = t; i < S_; i += 1024) {
                int l = i ^ j;
                if (l > i) {
                    unsigned long long a = keys[i], c = keys[l];
                    bool sw = ((i & k) == 0) ? (a < c) : (a > c);
                    if (sw) { keys[i] = c; keys[l] = a; }
                }
            }
            __syncthreads();
        }
    }
    if (t < KEEP) {
        int idx = (S_ - 1) - (int)(unsigned int)(keys[t] & 0xFFFFFFFFull);
        g_rowmap[b * KEEP + t] = b * S_ + idx;
    }
}

// ------------------------- attention (lazy-rescale online softmax) -----------
__global__ __launch_bounds__(128) void attn_kernel() {
    int bh = blockIdx.x;
    int b = bh >> 3, h = bh & 7;
    int q = blockIdx.y * 128 + threadIdx.x;
    const float scale = 0.17677669529663687f;  // 1/sqrt(32)

    __shared__ float Ks[128][32];
    __shared__ float Vs[128][32];

    float qr[HD_];
    const float* qp = g_Q + ((size_t)(b * S_ + q)) * D_ + h * HD_;
    #pragma unroll
    for (int d = 0; d < HD_; d++) qr[d] = qp[d] * scale;

    float o[HD_] = {};
    float m = -CUDART_INF_F, lsum = 0.f;

    for (int j0 = 0; j0 < KEEP; j0 += 128) {
        int cnt = min(128, KEEP - j0);
        __syncthreads();
        for (int idx = threadIdx.x; idx < cnt * HD_; idx += 128) {
            int r = idx >> 5, c = idx & 31;
            const float* src = g_KV + ((size_t)(b * KEEP + j0 + r)) * (2 * D_) + h * HD_;
            Ks[r][c] = src[c];
            Vs[r][c] = src[D_ + c];
        }
        __syncthreads();
        for (int j = 0; j < cnt; j++) {
            float s = 0.f;
            #pragma unroll
            for (int d = 0; d < HD_; d++) s = fmaf(qr[d], Ks[j][d], s);
            if (s <= m) {
                float p = __expf(s - m);
                lsum += p;
                #pragma unroll
                for (int d = 0; d < HD_; d++) o[d] = fmaf(p, Vs[j][d], o[d]);
            } else {
                float corr = __expf(m - s);      // 0 on first key (m = -inf)
                lsum = fmaf(lsum, corr, 1.f);
                #pragma unroll
                for (int d = 0; d < HD_; d++) o[d] = fmaf(o[d], corr, Vs[j][d]);
                m = s;
            }
        }
    }
    float inv = 1.f / lsum;
    float* op = g_attn + ((size_t)(b * S_ + q)) * D_ + h * HD_;
    #pragma unroll
    for (int d = 0; d < HD_; d++) op[d] = o[d] * inv;
}

// ------------------------- host launch ---------------------------------------
extern "C" void kernel_launch(void* const* d_in, const int* in_sizes, int n_in,
                              void* d_out, int out_size) {
    const float* x       = (const float*)d_in[0];
    const float* w_in    = (const float*)d_in[1];
    const float* b_in    = (const float*)d_in[2];
    const float* w_out   = (const float*)d_in[3];
    const float* b_out   = (const float*)d_in[4];
    const float* gate_w1 = (const float*)d_in[5];
    const float* gate_b1 = (const float*)d_in[6];
    const float* gate_w2 = (const float*)d_in[7];
    const float* gate_b2 = (const float*)d_in[8];
    float* out = (float*)d_out;

    void *pQ, *pKV, *pAttn, *pRowmap, *pH;
    void *pXhi, *pXlo, *pAthi, *pAtlo, *pWinhi, *pWinlo, *pWouthi, *pWoutlo;
    cudaGetSymbolAddress(&pQ, g_Q);
    cudaGetSymbolAddress(&pKV, g_KV);
    cudaGetSymbolAddress(&pAttn, g_attn);
    cudaGetSymbolAddress(&pRowmap, g_rowmap);
    cudaGetSymbolAddress(&pH, g_h);
    cudaGetSymbolAddress(&pXhi, g_xhi);   cudaGetSymbolAddress(&pXlo, g_xlo);
    cudaGetSymbolAddress(&pAthi, g_athi); cudaGetSymbolAddress(&pAtlo, g_atlo);
    cudaGetSymbolAddress(&pWinhi, g_winhi);   cudaGetSymbolAddress(&pWinlo, g_winlo);
    cudaGetSymbolAddress(&pWouthi, g_wouthi); cudaGetSymbolAddress(&pWoutlo, g_woutlo);

    cudaFuncSetAttribute(gemm_bf16, cudaFuncAttributeMaxDynamicSharedMemorySize, SMEM_GM);

    // 1. gate hidden layer (exact fp32 — feeds discrete top-k)
    gate_gemm<<<ROWS / 64, 256>>>(x, gate_w1, gate_b1, (float*)pH);
    gate2_kernel<<<ROWS / 8, 256>>>(gate_w2, gate_b2);
    topk_kernel<<<B_, 1024>>>();

    // 2. pre-split operands into bf16 hi/lo
    convert_split<<<(ROWS * D_ / 4 + 255) / 256, 256>>>(
        (const float4*)x, (__nv_bfloat162*)pXhi, (__nv_bfloat162*)pXlo, ROWS * D_ / 4);
    convert_split<<<(3 * D_ * D_ / 4 + 255) / 256, 256>>>(
        (const float4*)w_in, (__nv_bfloat162*)pWinhi, (__nv_bfloat162*)pWinlo, 3 * D_ * D_ / 4);
    convert_split<<<(D_ * D_ / 4 + 255) / 256, 256>>>(
        (const float4*)w_out, (__nv_bfloat162*)pWouthi, (__nv_bfloat162*)pWoutlo, D_ * D_ / 4);

    // 3. Q = x @ Wq^T   [8192 x 256]
    gemm_bf16<<<dim3(D_ / 128, ROWS / 128), 256, SMEM_GM>>>(
        (const __nv_bfloat16*)pXhi, (const __nv_bfloat16*)pXlo, nullptr,
        (const __nv_bfloat16*)pWinhi, (const __nv_bfloat16*)pWinlo,
        b_in, (float*)pQ, ROWS, D_);

    // 4. K,V at kept rows  [816 x 512]
    gemm_bf16<<<dim3((2 * D_) / 128, (KV_ROWS + 127) / 128), 256, SMEM_GM>>>(
        (const __nv_bfloat16*)pXhi, (const __nv_bfloat16*)pXlo, (const int*)pRowmap,
        (const __nv_bfloat16*)pWinhi + D_ * D_, (const __nv_bfloat16*)pWinlo + D_ * D_,
        b_in + D_, (float*)pKV, KV_ROWS, 2 * D_);

    // 5. attention over 204 compacted keys
    attn_kernel<<<dim3(B_ * H_, S_ / 128), 128>>>();

    // 6. split attention output, then out projection
    convert_split<<<(ROWS * D_ / 4 + 255) / 256, 256>>>(
        (const float4*)pAttn, (__nv_bfloat162*)pAthi, (__nv_bfloat162*)pAtlo, ROWS * D_ / 4);
    gemm_bf16<<<dim3(D_ / 128, ROWS / 128), 256, SMEM_GM>>>(
        (const __nv_bfloat16*)pAthi, (const __nv_bfloat16*)pAtlo, nullptr,
        (const __nv_bfloat16*)pWouthi, (const __nv_bfloat16*)pWoutlo,
        b_out, out, ROWS, D_);
}